// round 1
// baseline (speedup 1.0000x reference)
#include <cuda_runtime.h>
#include <math.h>

// IDWT 1D (db4). out[row, j] = sum_r L[row,r]*mL[r,j] + H[row,r]*mH[r,j]
// mL[r,j] = band_low[j+3-2r] (banded, 8 taps). Each output j has exactly
// 4 L-taps and 4 H-taps (clipped at boundaries).
//
// even j=2i  : L[i+1]*bl1 + L[i]*bl3 + L[i-1]*bl5 + L[i-2]*bl7  (+ H with bh)
// odd  j=2i+1: L[i+2]*bl0 + L[i+1]*bl2 + L[i]*bl4 + L[i-1]*bl6  (+ H with bh)
//
// Filter taps are read from the input matrices themselves (row r=2 holds
// band[k] at column k+1), so the kernel is correct for whatever matrices
// the harness supplies (as long as they have this banded structure).

__global__ void idwt1d_db4_kernel(const float* __restrict__ L,
                                  const float* __restrict__ H,
                                  const float* __restrict__ mL,
                                  const float* __restrict__ mH,
                                  float* __restrict__ out,
                                  int Lh)
{
    const int W = 2 * Lh;              // output row length
    __shared__ float cf[16];           // bl[0..7], bh[0..7]

    if (threadIdx.x < 16) {
        const float* M = (threadIdx.x < 8) ? mL : mH;
        // band[k] = M[2, k+1]  (row stride of matrix is W)
        cf[threadIdx.x] = M[(size_t)2 * W + (threadIdx.x & 7) + 1];
    }
    __syncthreads();

    const float bl0 = cf[0], bl1 = cf[1], bl2 = cf[2], bl3 = cf[3];
    const float bl4 = cf[4], bl5 = cf[5], bl6 = cf[6], bl7 = cf[7];
    const float bh0 = cf[8], bh1 = cf[9], bh2 = cf[10], bh3 = cf[11];
    const float bh4 = cf[12], bh5 = cf[13], bh6 = cf[14], bh7 = cf[15];

    const int row   = blockIdx.y;
    const int quads = W >> 2;          // float4 outputs per row
    const int t     = blockIdx.x * blockDim.x + threadIdx.x;
    if (t >= quads) return;

    const float* __restrict__ Lr = L + (size_t)row * Lh;
    const float* __restrict__ Hr = H + (size_t)row * Lh;

    const int i0 = 2 * t;              // base coarse index; need L/H[i0-2 .. i0+3]

    float l0, l1, l2, l3, l4, l5;
    float h0, h1, h2, h3, h4, h5;

    if (t > 0 && t < quads - 1) {
        // interior: i0-2 >= 0 and i0+3 <= Lh-1, all indices even-aligned -> float2
        float2 a = *reinterpret_cast<const float2*>(Lr + i0 - 2);
        float2 b = *reinterpret_cast<const float2*>(Lr + i0);
        float2 c = *reinterpret_cast<const float2*>(Lr + i0 + 2);
        l0 = a.x; l1 = a.y; l2 = b.x; l3 = b.y; l4 = c.x; l5 = c.y;
        float2 d = *reinterpret_cast<const float2*>(Hr + i0 - 2);
        float2 e = *reinterpret_cast<const float2*>(Hr + i0);
        float2 f = *reinterpret_cast<const float2*>(Hr + i0 + 2);
        h0 = d.x; h1 = d.y; h2 = e.x; h3 = e.y; h4 = f.x; h5 = f.y;
    } else {
        // boundary: predicated scalar loads (out-of-range taps are zero)
        float lv[6], hv[6];
#pragma unroll
        for (int m = 0; m < 6; m++) {
            int r = i0 - 2 + m;
            bool ok = (r >= 0) && (r < Lh);
            lv[m] = ok ? Lr[r] : 0.0f;
            hv[m] = ok ? Hr[r] : 0.0f;
        }
        l0 = lv[0]; l1 = lv[1]; l2 = lv[2]; l3 = lv[3]; l4 = lv[4]; l5 = lv[5];
        h0 = hv[0]; h1 = hv[1]; h2 = hv[2]; h3 = hv[3]; h4 = hv[4]; h5 = hv[5];
    }

    // l0=L[i0-2] l1=L[i0-1] l2=L[i0] l3=L[i0+1] l4=L[i0+2] l5=L[i0+3]
    float4 o;
    // j = 2*i0 (even, i=i0)
    o.x = fmaf(l3, bl1, fmaf(l2, bl3, fmaf(l1, bl5, l0 * bl7)))
        + fmaf(h3, bh1, fmaf(h2, bh3, fmaf(h1, bh5, h0 * bh7)));
    // j = 2*i0+1 (odd, i=i0)
    o.y = fmaf(l4, bl0, fmaf(l3, bl2, fmaf(l2, bl4, l1 * bl6)))
        + fmaf(h4, bh0, fmaf(h3, bh2, fmaf(h2, bh4, h1 * bh6)));
    // j = 2*(i0+1) (even, i=i0+1)
    o.z = fmaf(l4, bl1, fmaf(l3, bl3, fmaf(l2, bl5, l1 * bl7)))
        + fmaf(h4, bh1, fmaf(h3, bh3, fmaf(h2, bh5, h1 * bh7)));
    // j = 2*(i0+1)+1 (odd, i=i0+1)
    o.w = fmaf(l5, bl0, fmaf(l4, bl2, fmaf(l3, bl4, l2 * bl6)))
        + fmaf(h5, bh0, fmaf(h4, bh2, fmaf(h3, bh4, h2 * bh6)));

    reinterpret_cast<float4*>(out + (size_t)row * W)[t] = o;
}

extern "C" void kernel_launch(void* const* d_in, const int* in_sizes, int n_in,
                              void* d_out, int out_size)
{
    const float* L  = (const float*)d_in[0];
    const float* H  = (const float*)d_in[1];
    const float* mL = (const float*)d_in[2];
    const float* mH = (const float*)d_in[3];
    float* out = (float*)d_out;

    // matrix is (Lh, 2*Lh) -> Lh = sqrt(size/2)
    long long msz = (long long)in_sizes[2];
    int Lh   = (int)(sqrt((double)(msz / 2)) + 0.5);
    int rows = in_sizes[0] / Lh;       // N*C
    int W    = 2 * Lh;
    int quads = W >> 2;

    dim3 block(256);
    dim3 grid((quads + block.x - 1) / block.x, rows);
    idwt1d_db4_kernel<<<grid, block>>>(L, H, mL, mH, out, Lh);
}

// round 3
// speedup vs baseline: 1.0152x; 1.0152x over previous
#include <cuda_runtime.h>
#include <math.h>

// IDWT 1D (db4): out[row, 2i]   = sum_k L[i+1-k?]... banded synthesis.
//   even j=2i  : L[i+1]*bl1 + L[i]*bl3 + L[i-1]*bl5 + L[i-2]*bl7  (+ H w/ bh)
//   odd  j=2i+1: L[i+2]*bl0 + L[i+1]*bl2 + L[i]*bl4 + L[i-1]*bl6  (+ H w/ bh)
// Taps read from matrix row r=2 (holds band[k] at column k+1).
//
// Each thread: 1 float4 load of L, 1 of H (aligned), halo via warp shuffle,
// 8 outputs = 2 float4 streaming stores.

__global__ void idwt1d_db4_kernel(const float* __restrict__ L,
                                  const float* __restrict__ H,
                                  const float* __restrict__ mL,
                                  const float* __restrict__ mH,
                                  float* __restrict__ out,
                                  int Lh)
{
    const int W = 2 * Lh;
    __shared__ float cf[16];
    if (threadIdx.x < 16) {
        const float* M = (threadIdx.x < 8) ? mL : mH;
        cf[threadIdx.x] = M[(size_t)2 * W + (threadIdx.x & 7) + 1];
    }
    __syncthreads();

    const float bl0 = cf[0], bl1 = cf[1], bl2 = cf[2], bl3 = cf[3];
    const float bl4 = cf[4], bl5 = cf[5], bl6 = cf[6], bl7 = cf[7];
    const float bh0 = cf[8], bh1 = cf[9], bh2 = cf[10], bh3 = cf[11];
    const float bh4 = cf[12], bh5 = cf[13], bh6 = cf[14], bh7 = cf[15];

    const int row = blockIdx.y;
    const int nt  = Lh >> 2;                       // threads per row (coarse quads)
    const int t   = blockIdx.x * blockDim.x + threadIdx.x;
    if (t >= nt) return;

    const int lane = threadIdx.x & 31;
    const int c0   = 4 * t;                        // coarse base; this thread owns L/H[c0..c0+3]

    const float* __restrict__ Lr = L + (size_t)row * Lh;
    const float* __restrict__ Hr = H + (size_t)row * Lh;

    const float4 l = *reinterpret_cast<const float4*>(Lr + c0);
    const float4 h = *reinterpret_cast<const float4*>(Hr + c0);

    // Halo from neighboring lanes (adjacent lanes = adjacent coarse quads).
    float lm2 = __shfl_up_sync(0xffffffffu, l.z, 1);
    float lm1 = __shfl_up_sync(0xffffffffu, l.w, 1);
    float hm2 = __shfl_up_sync(0xffffffffu, h.z, 1);
    float hm1 = __shfl_up_sync(0xffffffffu, h.w, 1);
    float lp4 = __shfl_down_sync(0xffffffffu, l.x, 1);
    float lp5 = __shfl_down_sync(0xffffffffu, l.y, 1);
    float hp4 = __shfl_down_sync(0xffffffffu, h.x, 1);
    float hp5 = __shfl_down_sync(0xffffffffu, h.y, 1);

    if (lane == 0) {                               // warp-edge fixup (rows are warp-aligned)
        lm2 = (c0 >= 2) ? Lr[c0 - 2] : 0.0f;
        lm1 = (c0 >= 1) ? Lr[c0 - 1] : 0.0f;
        hm2 = (c0 >= 2) ? Hr[c0 - 2] : 0.0f;
        hm1 = (c0 >= 1) ? Hr[c0 - 1] : 0.0f;
    }
    if (lane == 31) {
        lp4 = (c0 + 4 < Lh) ? Lr[c0 + 4] : 0.0f;
        lp5 = (c0 + 5 < Lh) ? Lr[c0 + 5] : 0.0f;
        hp4 = (c0 + 4 < Lh) ? Hr[c0 + 4] : 0.0f;
        hp5 = (c0 + 5 < Lh) ? Hr[c0 + 5] : 0.0f;
    }

    // la[k] = L[c0-2+k], k=0..7
    const float la[8] = { lm2, lm1, l.x, l.y, l.z, l.w, lp4, lp5 };
    const float ha[8] = { hm2, hm1, h.x, h.y, h.z, h.w, hp4, hp5 };

    float o[8];
#pragma unroll
    for (int m = 0; m < 4; m++) {
        // even j = 2*(c0+m): taps la[m..m+3]
        o[2 * m] =
            fmaf(la[m + 3], bl1, fmaf(la[m + 2], bl3, fmaf(la[m + 1], bl5, la[m] * bl7))) +
            fmaf(ha[m + 3], bh1, fmaf(ha[m + 2], bh3, fmaf(ha[m + 1], bh5, ha[m] * bh7)));
        // odd j = 2*(c0+m)+1: taps la[m+1..m+4]
        o[2 * m + 1] =
            fmaf(la[m + 4], bl0, fmaf(la[m + 3], bl2, fmaf(la[m + 2], bl4, la[m + 1] * bl6))) +
            fmaf(ha[m + 4], bh0, fmaf(ha[m + 3], bh2, fmaf(ha[m + 2], bh4, ha[m + 1] * bh6)));
    }

    float4* op = reinterpret_cast<float4*>(out + (size_t)row * W + 8 * (size_t)t);
    __stcs(op,     make_float4(o[0], o[1], o[2], o[3]));
    __stcs(op + 1, make_float4(o[4], o[5], o[6], o[7]));
}

extern "C" void kernel_launch(void* const* d_in, const int* in_sizes, int n_in,
                              void* d_out, int out_size)
{
    const float* L  = (const float*)d_in[0];
    const float* H  = (const float*)d_in[1];
    const float* mL = (const float*)d_in[2];
    const float* mH = (const float*)d_in[3];
    float* out = (float*)d_out;

    long long msz = (long long)in_sizes[2];
    int Lh   = (int)(sqrt((double)(msz / 2)) + 0.5);
    int rows = in_sizes[0] / Lh;                   // N*C
    int nt   = Lh >> 2;                            // threads per row

    dim3 block(256);
    dim3 grid((nt + block.x - 1) / block.x, rows);
    idwt1d_db4_kernel<<<grid, block>>>(L, H, mL, mH, out, Lh);
}